// round 13
// baseline (speedup 1.0000x reference)
#include <cuda_runtime.h>
#include <math.h>

#define B_BATCH 128
#define D_DIM   2048
#define P_DIM   16000
#define THREADS 1024

static __device__ float g_sAcc[2 * D_DIM];
static __device__ float g_wAcc[2 * D_DIM];
static __device__ float2 g_t128[128];
static __device__ float2 g_t125[125];
static __device__ float2 g_tS[125];

// ---------------------------------------------------------------------------
// Kernel 0: zero the moment accumulators (graph replays reuse them).
// ---------------------------------------------------------------------------
__global__ void zero_kernel() {
    int i = blockIdx.x * blockDim.x + threadIdx.x;
    if (i < 2 * D_DIM) { g_sAcc[i] = 0.0f; g_wAcc[i] = 0.0f; }
}

// ---------------------------------------------------------------------------
// Kernel 1: moment partial sums over HALF-rows (8192 scan blocks, 256 thr),
// accumulated with atomicAdd (exact: all partials are integers < 2^14).
// Block 8192 computes the FFT twiddle tables concurrently.
// ---------------------------------------------------------------------------
#define EX_THREADS 256
#define HALF_F4    2000              // float4s per half-row

__global__ void __launch_bounds__(EX_THREADS)
extract_kernel(const float* __restrict__ C1, const float* __restrict__ C2) {
    const int tid = threadIdx.x;
    if (blockIdx.x == 4 * D_DIM) {   // twiddle block
        const double TWO_PI = 6.283185307179586476925286766559;
        for (int t = tid; t < 128; t += EX_THREADS) {
            double s, c; sincos(-TWO_PI * (double)t / 128.0, &s, &c);
            g_t128[t] = make_float2((float)c, (float)s);
        }
        for (int t = tid; t < 125; t += EX_THREADS) {
            double s, c;
            sincos(-TWO_PI * (double)t / 125.0, &s, &c);
            g_t125[t] = make_float2((float)c, (float)s);
            sincos(-TWO_PI * (double)t / 16000.0, &s, &c);
            g_tS[t] = make_float2((float)c, (float)s);
        }
        return;
    }
    const int row  = blockIdx.x >> 1;        // 0..4095
    const int half = blockIdx.x & 1;
    const float4* b4 = (const float4*)((row < D_DIM)
                        ? (C1 + (size_t)row * P_DIM)
                        : (C2 + (size_t)(row - D_DIM) * P_DIM));
    b4 += half * HALF_F4;
    float4 v[8];
#pragma unroll
    for (int k = 0; k < 8; k++) {
        int i = k * EX_THREADS + tid;
        v[k] = (i < HALF_F4) ? b4[i] : make_float4(0.0f, 0.0f, 0.0f, 0.0f);
    }
    float s = 0.0f, w = 0.0f;
#pragma unroll
    for (int k = 0; k < 8; k++) {
        int i = k * EX_THREADS + tid;
        float p0 = (float)(4 * (half * HALF_F4 + i));
        float sv = (v[k].x + v[k].y) + (v[k].z + v[k].w);
        s += sv;
        w += p0 * sv + (v[k].y + 2.0f * v[k].z + 3.0f * v[k].w);
    }
#pragma unroll
    for (int o = 16; o > 0; o >>= 1) {
        s += __shfl_down_sync(0xFFFFFFFFu, s, o);
        w += __shfl_down_sync(0xFFFFFFFFu, w, o);
    }
    __shared__ float ss[EX_THREADS / 32], sw[EX_THREADS / 32];
    int lane = tid & 31, warp = tid >> 5;
    if (lane == 0) { ss[warp] = s; sw[warp] = w; }
    __syncthreads();
    if (warp == 0) {
        s = (lane < EX_THREADS / 32) ? ss[lane] : 0.0f;
        w = (lane < EX_THREADS / 32) ? sw[lane] : 0.0f;
#pragma unroll
        for (int o = EX_THREADS / 64; o > 0; o >>= 1) {
            s += __shfl_down_sync(0xFFFFFFFFu, s, o);
            w += __shfl_down_sync(0xFFFFFFFFu, w, o);
        }
        if (lane == 0) {
            atomicAdd(&g_sAcc[row], s);
            atomicAdd(&g_wAcc[row], w);
        }
    }
}

// base-5 digit reversal of 3 digits (involution), x in [0,125)
__device__ __forceinline__ int dr5(int x) {
    int a = x / 25;
    int rem = x - 25 * a;
    int b = rem / 5;
    int c = rem - 5 * b;
    return c * 25 + b * 5 + a;
}

typedef float2 cplx;
__device__ __forceinline__ cplx cmul(cplx a, cplx b) {
    return make_float2(a.x * b.x - a.y * b.y, a.x * b.y + a.y * b.x);
}
__device__ __forceinline__ cplx cmulc(cplx a, cplx b) {   // a * conj(b)
    return make_float2(a.x * b.x + a.y * b.y, a.y * b.x - a.x * b.y);
}
__device__ __forceinline__ cplx cadd(cplx a, cplx b) { return make_float2(a.x + b.x, a.y + b.y); }
__device__ __forceinline__ cplx csub(cplx a, cplx b) { return make_float2(a.x - b.x, a.y - b.y); }
__device__ __forceinline__ cplx mul_negi(cplx v) { return make_float2(v.y, -v.x); }   // v * (-i)
__device__ __forceinline__ cplx mul_posi(cplx v) { return make_float2(-v.y, v.x); }   // v * (+i)

#define RHALF 0.70710678118654752f
#define C72  ( 0.30901699437494742f)
#define S72  ( 0.95105651629515357f)
#define C144 (-0.80901699437494745f)
#define S144 ( 0.58778525229247314f)

// 5-point butterflies, in place, no twiddle.
__device__ __forceinline__ void bf5_fwd(cplx a[5]) {
    cplx t1 = cadd(a[1], a[4]), t3 = csub(a[1], a[4]);
    cplx t2 = cadd(a[2], a[3]), t4 = csub(a[2], a[3]);
    cplx a0 = a[0];
    cplx m1 = make_float2(a0.x + C72 * t1.x + C144 * t2.x, a0.y + C72 * t1.y + C144 * t2.y);
    cplx m2 = make_float2(a0.x + C144 * t1.x + C72 * t2.x, a0.y + C144 * t1.y + C72 * t2.y);
    cplx v1 = make_float2(S72 * t3.x + S144 * t4.x, S72 * t3.y + S144 * t4.y);
    cplx v2 = make_float2(S144 * t3.x - S72 * t4.x, S144 * t3.y - S72 * t4.y);
    a[0] = make_float2(a0.x + t1.x + t2.x, a0.y + t1.y + t2.y);
    a[1] = make_float2(m1.x + v1.y, m1.y - v1.x);
    a[2] = make_float2(m2.x + v2.y, m2.y - v2.x);
    a[3] = make_float2(m2.x - v2.y, m2.y + v2.x);
    a[4] = make_float2(m1.x - v1.y, m1.y + v1.x);
}
__device__ __forceinline__ void bf5_inv(cplx a[5]) {
    cplx t1 = cadd(a[1], a[4]), t3 = csub(a[1], a[4]);
    cplx t2 = cadd(a[2], a[3]), t4 = csub(a[2], a[3]);
    cplx a0 = a[0];
    cplx m1 = make_float2(a0.x + C72 * t1.x + C144 * t2.x, a0.y + C72 * t1.y + C144 * t2.y);
    cplx m2 = make_float2(a0.x + C144 * t1.x + C72 * t2.x, a0.y + C144 * t1.y + C72 * t2.y);
    cplx v1 = make_float2(S72 * t3.x + S144 * t4.x, S72 * t3.y + S144 * t4.y);
    cplx v2 = make_float2(S144 * t3.x - S72 * t4.x, S144 * t3.y - S72 * t4.y);
    a[0] = make_float2(a0.x + t1.x + t2.x, a0.y + t1.y + t2.y);
    a[1] = make_float2(m1.x - v1.y, m1.y + v1.x);
    a[2] = make_float2(m2.x - v2.y, m2.y + v2.x);
    a[3] = make_float2(m2.x + v2.y, m2.y - v2.x);
    a[4] = make_float2(m1.x + v1.y, m1.y - v1.x);
}

// Radix-8 DIT with j = 0: constant twiddles.
__device__ __forceinline__ void radix8_dit_j0(cplx x[8]) {
#pragma unroll
    for (int t = 0; t < 8; t += 2) {
        cplx v = x[t + 1];
        x[t + 1] = csub(x[t], v);
        x[t]     = cadd(x[t], v);
    }
#pragma unroll
    for (int b0 = 0; b0 < 8; b0 += 4) {
        {
            cplx v = x[b0 + 2];
            x[b0 + 2] = csub(x[b0], v);
            x[b0]     = cadd(x[b0], v);
        }
        {
            cplx v = mul_negi(x[b0 + 3]);
            x[b0 + 3] = csub(x[b0 + 1], v);
            x[b0 + 1] = cadd(x[b0 + 1], v);
        }
    }
    {
        cplx v = x[4];
        x[4] = csub(x[0], v); x[0] = cadd(x[0], v);
    }
    {
        cplx h = x[5];
        cplx v = make_float2(RHALF * (h.x + h.y), RHALF * (h.y - h.x));
        x[5] = csub(x[1], v); x[1] = cadd(x[1], v);
    }
    {
        cplx v = mul_negi(x[6]);
        x[6] = csub(x[2], v); x[2] = cadd(x[2], v);
    }
    {
        cplx h = x[7];
        cplx v = make_float2(RHALF * (h.y - h.x), -RHALF * (h.x + h.y));
        x[7] = csub(x[3], v); x[3] = cadd(x[3], v);
    }
}

// Radix-8 DIF with j = 0 (inverse, conj twiddles).
__device__ __forceinline__ void radix8_dif_j0(cplx x[8]) {
    {
        cplx u = x[0], v = x[4];
        x[0] = cadd(u, v); x[4] = csub(u, v);
    }
    {
        cplx u = x[1], v = x[5];
        x[1] = cadd(u, v);
        cplx d = csub(u, v);
        x[5] = make_float2(RHALF * (d.x - d.y), RHALF * (d.x + d.y));
    }
    {
        cplx u = x[2], v = x[6];
        x[2] = cadd(u, v);
        x[6] = mul_posi(csub(u, v));
    }
    {
        cplx u = x[3], v = x[7];
        x[3] = cadd(u, v);
        cplx d = csub(u, v);
        x[7] = make_float2(-RHALF * (d.x + d.y), RHALF * (d.x - d.y));
    }
#pragma unroll
    for (int b0 = 0; b0 < 8; b0 += 4) {
        {
            cplx u = x[b0], v = x[b0 + 2];
            x[b0]     = cadd(u, v);
            x[b0 + 2] = csub(u, v);
        }
        {
            cplx u = x[b0 + 1], v = x[b0 + 3];
            x[b0 + 1] = cadd(u, v);
            x[b0 + 3] = mul_posi(csub(u, v));
        }
    }
#pragma unroll
    for (int t = 0; t < 8; t += 2) {
        cplx u = x[t], v = x[t + 1];
        x[t]     = cadd(u, v);
        x[t + 1] = csub(u, v);
    }
}

// Radix-16 DIT: radix-2 stages 3..6 on x[t] = row (j + 8t), j in [0,8).
__device__ __forceinline__ void radix16_dit(cplx x[16], int j, const cplx* t128) {
    cplx wa = t128[8 * j];
#pragma unroll
    for (int t = 0; t < 16; t += 2) {
        cplx v = cmul(x[t + 1], wa);
        x[t + 1] = csub(x[t], v);
        x[t]     = cadd(x[t], v);
    }
    cplx wb0 = t128[4 * j];
    cplx wb1 = t128[4 * j + 32];
#pragma unroll
    for (int b0 = 0; b0 < 16; b0 += 4) {
        {
            cplx v = cmul(x[b0 + 2], wb0);
            x[b0 + 2] = csub(x[b0], v);
            x[b0]     = cadd(x[b0], v);
        }
        {
            cplx v = cmul(x[b0 + 3], wb1);
            x[b0 + 3] = csub(x[b0 + 1], v);
            x[b0 + 1] = cadd(x[b0 + 1], v);
        }
    }
#pragma unroll
    for (int grp = 0; grp < 16; grp += 8) {
#pragma unroll
        for (int q = 0; q < 4; q++) {
            cplx w = t128[2 * j + 16 * q];
            cplx v = cmul(x[grp + q + 4], w);
            x[grp + q + 4] = csub(x[grp + q], v);
            x[grp + q]     = cadd(x[grp + q], v);
        }
    }
#pragma unroll
    for (int t = 0; t < 8; t++) {
        cplx w = t128[j + 8 * t];
        cplx v = cmul(x[t + 8], w);
        x[t + 8] = csub(x[t], v);
        x[t]     = cadd(x[t], v);
    }
}

// Radix-16 DIF: inverse stages 6..3 with conj twiddles.
__device__ __forceinline__ void radix16_dif(cplx x[16], int j, const cplx* t128) {
#pragma unroll
    for (int t = 0; t < 8; t++) {
        cplx w = t128[j + 8 * t];
        cplx u = x[t], v = x[t + 8];
        x[t]     = cadd(u, v);
        x[t + 8] = cmulc(csub(u, v), w);
    }
#pragma unroll
    for (int grp = 0; grp < 16; grp += 8) {
#pragma unroll
        for (int q = 0; q < 4; q++) {
            cplx w = t128[2 * j + 16 * q];
            cplx u = x[grp + q], v = x[grp + q + 4];
            x[grp + q]     = cadd(u, v);
            x[grp + q + 4] = cmulc(csub(u, v), w);
        }
    }
    cplx wb0 = t128[4 * j];
    cplx wb1 = t128[4 * j + 32];
#pragma unroll
    for (int b0 = 0; b0 < 16; b0 += 4) {
        {
            cplx u = x[b0], v = x[b0 + 2];
            x[b0]     = cadd(u, v);
            x[b0 + 2] = cmulc(csub(u, v), wb0);
        }
        {
            cplx u = x[b0 + 1], v = x[b0 + 3];
            x[b0 + 1] = cadd(u, v);
            x[b0 + 3] = cmulc(csub(u, v), wb1);
        }
    }
    cplx wa = t128[8 * j];
#pragma unroll
    for (int t = 0; t < 16; t += 2) {
        cplx u = x[t], v = x[t + 1];
        x[t]     = cadd(u, v);
        x[t + 1] = cmulc(csub(u, v), wa);
    }
}

// ---------------------------------------------------------------------------
// Kernel 2: z = y1 + i*y2, Z = FFT_16000 (128x125 four-step), Hermitian split
// + pointwise multiply, phi = Re(IFFT)/N.  [verified R10 FFT structure]
// Count-sketch (idx, sgn) recomputed inline from the moment accumulators.
// ---------------------------------------------------------------------------
__global__ void __launch_bounds__(THREADS)
mcb_fft_kernel(const float* __restrict__ x1, const float* __restrict__ x2,
               float* __restrict__ out) {
    extern __shared__ cplx S[];                // 16000 complex = 128000 B
    __shared__ cplx t128[128];
    __shared__ cplx t125[125];
    __shared__ cplx tS[125];

    const int tid = threadIdx.x;
    const int b   = blockIdx.x;

    if (tid < 128) t128[tid] = g_t128[tid];
    else if (tid < 256) { if (tid - 128 < 125) t125[tid - 128] = g_t125[tid - 128]; }
    else if (tid < 384) { if (tid - 256 < 125) tS[tid - 256]   = g_tS[tid - 256]; }
    for (int i = tid; i < P_DIM; i += THREADS) S[i] = make_float2(0.0f, 0.0f);
    __syncthreads();

    // scatter: y1 -> real, y2 -> imag, rows bit-reversed for the DIT stages
    for (int d = tid; d < D_DIM; d += THREADS) {
        float sg = g_sAcc[d];
        int p = (int)rintf(g_wAcc[d] * sg);
        float v = x1[b * D_DIM + d] * sg;
        int n1 = p / 125, n2 = p - n1 * 125;
        int r = __brev(n1) >> 25;
        atomicAdd(&S[r * 125 + n2].x, v);
        sg = g_sAcc[D_DIM + d];
        p = (int)rintf(g_wAcc[D_DIM + d] * sg);
        v = x2[b * D_DIM + d] * sg;
        n1 = p / 125; n2 = p - n1 * 125;
        r = __brev(n1) >> 25;
        atomicAdd(&S[r * 125 + n2].y, v);
    }
    __syncthreads();

    // ---- forward radix-2 stages 0..2 (rows 8g+t, fixed col), j=0 specialized ----
    for (int idx = tid; idx < 2000; idx += THREADS) {
        int c = idx % 125;
        int g = idx / 125;
        int base = g * 1000 + c;
        cplx x[8];
#pragma unroll
        for (int t = 0; t < 8; t++) x[t] = S[base + t * 125];
        radix8_dit_j0(x);
#pragma unroll
        for (int t = 0; t < 8; t++) S[base + t * 125] = x[t];
    }
    __syncthreads();

    // ---- forward radix-2 stages 3..6 + inter-phase twiddle (radix-16) ----
    if (tid < 1000) {
        int c = tid % 125;
        int j = tid / 125;        // 0..7
        int base = j * 125 + c;
        cplx x[16];
#pragma unroll
        for (int t = 0; t < 16; t++) x[t] = S[base + t * 1000];
        radix16_dit(x, j, t128);
#pragma unroll
        for (int t = 0; t < 16; t++) {
            int k1 = j + 8 * t;
            int mm = c * k1;
            int q = mm / 125, rr = mm - q * 125;
            S[base + t * 1000] = cmul(x[t], cmul(t128[q], tS[rr]));
        }
    }
    __syncthreads();

    // ---- forward: 3 radix-5 DIF stages (length-125 row FFTs) ----
#pragma unroll
    for (int sidx = 0; sidx < 3; sidx++) {
        const int L = (sidx == 0) ? 125 : (sidx == 1) ? 25 : 5;
        const int m = L / 5;
        const int f = 125 / L;
        for (int idx = tid; idx < 3200; idx += THREADS) {
            int r  = idx & 127;
            int bj = idx >> 7;
            int j  = bj % m;
            int base = r * 125 + (bj / m) * L + j;
            cplx a[5];
            a[0] = S[base];
            a[1] = S[base + m];
            a[2] = S[base + 2 * m];
            a[3] = S[base + 3 * m];
            a[4] = S[base + 4 * m];
            bf5_fwd(a);
            int jf = j * f;
            S[base]         = a[0];
            S[base + m]     = cmul(a[1], t125[jf]);
            S[base + 2 * m] = cmul(a[2], t125[2 * jf]);
            S[base + 3 * m] = cmul(a[3], t125[3 * jf]);
            S[base + 4 * m] = cmul(a[4], t125[4 * jf]);
        }
        __syncthreads();
    }

    // ---- Hermitian split + pointwise multiply, in scrambled storage ----
    for (int k = tid; k <= 8000; k += THREADS) {
        if (k == 0) {
            cplx z = S[0];
            S[0] = make_float2(z.x * z.y, 0.0f);
        } else if (k == 8000) {
            const int addr = 64 * 125 + 62;
            cplx z = S[addr];
            S[addr] = make_float2(z.x * z.y, 0.0f);
        } else {
            int k1 = k & 127, k2 = k >> 7;
            int pa = k1 * 125 + dr5(k2);
            int kp = P_DIM - k;
            int k1p = kp & 127, k2p = kp >> 7;
            int pb = k1p * 125 + dr5(k2p);
            cplx A = S[pa];
            cplx Bv = S[pb];
            float F1r = 0.5f * (A.x + Bv.x), F1i = 0.5f * (A.y - Bv.y);
            float F2r = 0.5f * (A.y + Bv.y), F2i = 0.5f * (Bv.x - A.x);
            float Hr = F1r * F2r - F1i * F2i;
            float Hi = F1r * F2i + F1i * F2r;
            S[pa] = make_float2(Hr,  Hi);
            S[pb] = make_float2(Hr, -Hi);
        }
    }
    __syncthreads();

    // ---- inverse: 3 radix-5 DIT stages (rows), conj twiddles ----
#pragma unroll
    for (int sidx = 0; sidx < 3; sidx++) {
        const int L = (sidx == 0) ? 5 : (sidx == 1) ? 25 : 125;
        const int m = L / 5;
        const int f = 125 / L;
        for (int idx = tid; idx < 3200; idx += THREADS) {
            int r  = idx & 127;
            int bj = idx >> 7;
            int j  = bj % m;
            int base = r * 125 + (bj / m) * L + j;
            int jf = j * f;
            cplx a[5];
            a[0] = S[base];
            a[1] = cmulc(S[base + m],     t125[jf]);
            a[2] = cmulc(S[base + 2 * m], t125[2 * jf]);
            a[3] = cmulc(S[base + 3 * m], t125[3 * jf]);
            a[4] = cmulc(S[base + 4 * m], t125[4 * jf]);
            bf5_inv(a);
            S[base]         = a[0];
            S[base + m]     = a[1];
            S[base + 2 * m] = a[2];
            S[base + 3 * m] = a[3];
            S[base + 4 * m] = a[4];
        }
        __syncthreads();
    }

    // ---- inverse inter-phase twiddle (conj) + radix-2 stages 6..3 (radix-16) ----
    if (tid < 1000) {
        int c = tid % 125;
        int j = tid / 125;
        int base = j * 125 + c;
        cplx x[16];
#pragma unroll
        for (int t = 0; t < 16; t++) {
            int k1 = j + 8 * t;
            int mm = c * k1;
            int q = mm / 125, rr = mm - q * 125;
            x[t] = cmulc(S[base + t * 1000], cmul(t128[q], tS[rr]));
        }
        radix16_dif(x, j, t128);
#pragma unroll
        for (int t = 0; t < 16; t++) S[base + t * 1000] = x[t];
    }
    __syncthreads();

    // ---- inverse radix-2 stages 2..0 (j=0 specialized), fused with output ----
    const float scale = 1.0f / 16000.0f;
    for (int idx = tid; idx < 2000; idx += THREADS) {
        int c = idx % 125;
        int g = idx / 125;
        int base = g * 1000 + c;
        cplx x[8];
#pragma unroll
        for (int t = 0; t < 8; t++) x[t] = S[base + t * 125];
        radix8_dif_j0(x);
#pragma unroll
        for (int t = 0; t < 8; t++) {
            int n1 = __brev(8 * g + t) >> 25;
            out[b * P_DIM + n1 * 125 + c] = x[t].x * scale;
        }
    }
}

extern "C" void kernel_launch(void* const* d_in, const int* in_sizes, int n_in,
                              void* d_out, int out_size) {
    const float* x1 = (const float*)d_in[0];
    const float* x2 = (const float*)d_in[1];
    const float* C1 = (const float*)d_in[2];
    const float* C2 = (const float*)d_in[3];
    float* out = (float*)d_out;

    zero_kernel<<<(2 * D_DIM + 1023) / 1024, 1024>>>();
    extract_kernel<<<4 * D_DIM + 1, EX_THREADS>>>(C1, C2);

    const size_t smem = (size_t)P_DIM * sizeof(cplx);  // 128000 B
    cudaFuncSetAttribute(mcb_fft_kernel,
                         cudaFuncAttributeMaxDynamicSharedMemorySize, (int)smem);
    mcb_fft_kernel<<<B_BATCH, THREADS, smem>>>(x1, x2, out);
}

// round 14
// speedup vs baseline: 1.0005x; 1.0005x over previous
#include <cuda_runtime.h>
#include <math.h>

#define B_BATCH 128
#define D_DIM   2048
#define P_DIM   16000
#define THREADS 1024

// Per-half moment partials: [half][row].  Written unconditionally every
// launch (plain stores, no atomics) -> no zeroing needed, graph-safe.
static __device__ float g_s0[2 * D_DIM], g_s1[2 * D_DIM];
static __device__ float g_w0[2 * D_DIM], g_w1[2 * D_DIM];
static __device__ float2 g_t128[128];
static __device__ float2 g_t125[125];
static __device__ float2 g_tS[125];

// ---------------------------------------------------------------------------
// Kernel 1: moment partial sums over HALF-rows (8192 scan blocks, 256 thr).
// sgn = sum(C[row,:]), idx = sgn * sum(p*C[row,p]); exact in fp32.
// Block 8192 computes the FFT twiddle tables concurrently.
// ---------------------------------------------------------------------------
#define EX_THREADS 256
#define HALF_F4    2000              // float4s per half-row

__global__ void __launch_bounds__(EX_THREADS)
extract_kernel(const float* __restrict__ C1, const float* __restrict__ C2) {
    const int tid = threadIdx.x;
    if (blockIdx.x == 4 * D_DIM) {   // twiddle block
        const double TWO_PI = 6.283185307179586476925286766559;
        for (int t = tid; t < 128; t += EX_THREADS) {
            double s, c; sincos(-TWO_PI * (double)t / 128.0, &s, &c);
            g_t128[t] = make_float2((float)c, (float)s);
        }
        for (int t = tid; t < 125; t += EX_THREADS) {
            double s, c;
            sincos(-TWO_PI * (double)t / 125.0, &s, &c);
            g_t125[t] = make_float2((float)c, (float)s);
            sincos(-TWO_PI * (double)t / 16000.0, &s, &c);
            g_tS[t] = make_float2((float)c, (float)s);
        }
        return;
    }
    const int row  = blockIdx.x >> 1;        // 0..4095
    const int half = blockIdx.x & 1;
    const float4* b4 = (const float4*)((row < D_DIM)
                        ? (C1 + (size_t)row * P_DIM)
                        : (C2 + (size_t)(row - D_DIM) * P_DIM));
    b4 += half * HALF_F4;
    float4 v[8];
#pragma unroll
    for (int k = 0; k < 8; k++) {
        int i = k * EX_THREADS + tid;
        v[k] = (i < HALF_F4) ? b4[i] : make_float4(0.0f, 0.0f, 0.0f, 0.0f);
    }
    float s = 0.0f, w = 0.0f;
#pragma unroll
    for (int k = 0; k < 8; k++) {
        int i = k * EX_THREADS + tid;
        float p0 = (float)(4 * (half * HALF_F4 + i));
        float sv = (v[k].x + v[k].y) + (v[k].z + v[k].w);
        s += sv;
        w += p0 * sv + (v[k].y + 2.0f * v[k].z + 3.0f * v[k].w);
    }
#pragma unroll
    for (int o = 16; o > 0; o >>= 1) {
        s += __shfl_down_sync(0xFFFFFFFFu, s, o);
        w += __shfl_down_sync(0xFFFFFFFFu, w, o);
    }
    __shared__ float ss[EX_THREADS / 32], sw[EX_THREADS / 32];
    int lane = tid & 31, warp = tid >> 5;
    if (lane == 0) { ss[warp] = s; sw[warp] = w; }
    __syncthreads();
    if (warp == 0) {
        s = (lane < EX_THREADS / 32) ? ss[lane] : 0.0f;
        w = (lane < EX_THREADS / 32) ? sw[lane] : 0.0f;
#pragma unroll
        for (int o = EX_THREADS / 64; o > 0; o >>= 1) {
            s += __shfl_down_sync(0xFFFFFFFFu, s, o);
            w += __shfl_down_sync(0xFFFFFFFFu, w, o);
        }
        if (lane == 0) {
            if (half == 0) { g_s0[row] = s; g_w0[row] = w; }
            else           { g_s1[row] = s; g_w1[row] = w; }
        }
    }
}

// base-5 digit reversal of 3 digits (involution), x in [0,125)
__device__ __forceinline__ int dr5(int x) {
    int a = x / 25;
    int rem = x - 25 * a;
    int b = rem / 5;
    int c = rem - 5 * b;
    return c * 25 + b * 5 + a;
}

typedef float2 cplx;
__device__ __forceinline__ cplx cmul(cplx a, cplx b) {
    return make_float2(a.x * b.x - a.y * b.y, a.x * b.y + a.y * b.x);
}
__device__ __forceinline__ cplx cmulc(cplx a, cplx b) {   // a * conj(b)
    return make_float2(a.x * b.x + a.y * b.y, a.y * b.x - a.x * b.y);
}
__device__ __forceinline__ cplx cadd(cplx a, cplx b) { return make_float2(a.x + b.x, a.y + b.y); }
__device__ __forceinline__ cplx csub(cplx a, cplx b) { return make_float2(a.x - b.x, a.y - b.y); }
__device__ __forceinline__ cplx mul_negi(cplx v) { return make_float2(v.y, -v.x); }   // v * (-i)
__device__ __forceinline__ cplx mul_posi(cplx v) { return make_float2(-v.y, v.x); }   // v * (+i)

#define RHALF 0.70710678118654752f
#define C72  ( 0.30901699437494742f)
#define S72  ( 0.95105651629515357f)
#define C144 (-0.80901699437494745f)
#define S144 ( 0.58778525229247314f)

// 5-point butterflies, in place, no twiddle.
__device__ __forceinline__ void bf5_fwd(cplx a[5]) {
    cplx t1 = cadd(a[1], a[4]), t3 = csub(a[1], a[4]);
    cplx t2 = cadd(a[2], a[3]), t4 = csub(a[2], a[3]);
    cplx a0 = a[0];
    cplx m1 = make_float2(a0.x + C72 * t1.x + C144 * t2.x, a0.y + C72 * t1.y + C144 * t2.y);
    cplx m2 = make_float2(a0.x + C144 * t1.x + C72 * t2.x, a0.y + C144 * t1.y + C72 * t2.y);
    cplx v1 = make_float2(S72 * t3.x + S144 * t4.x, S72 * t3.y + S144 * t4.y);
    cplx v2 = make_float2(S144 * t3.x - S72 * t4.x, S144 * t3.y - S72 * t4.y);
    a[0] = make_float2(a0.x + t1.x + t2.x, a0.y + t1.y + t2.y);
    a[1] = make_float2(m1.x + v1.y, m1.y - v1.x);
    a[2] = make_float2(m2.x + v2.y, m2.y - v2.x);
    a[3] = make_float2(m2.x - v2.y, m2.y + v2.x);
    a[4] = make_float2(m1.x - v1.y, m1.y + v1.x);
}
__device__ __forceinline__ void bf5_inv(cplx a[5]) {
    cplx t1 = cadd(a[1], a[4]), t3 = csub(a[1], a[4]);
    cplx t2 = cadd(a[2], a[3]), t4 = csub(a[2], a[3]);
    cplx a0 = a[0];
    cplx m1 = make_float2(a0.x + C72 * t1.x + C144 * t2.x, a0.y + C72 * t1.y + C144 * t2.y);
    cplx m2 = make_float2(a0.x + C144 * t1.x + C72 * t2.x, a0.y + C144 * t1.y + C72 * t2.y);
    cplx v1 = make_float2(S72 * t3.x + S144 * t4.x, S72 * t3.y + S144 * t4.y);
    cplx v2 = make_float2(S144 * t3.x - S72 * t4.x, S144 * t3.y - S72 * t4.y);
    a[0] = make_float2(a0.x + t1.x + t2.x, a0.y + t1.y + t2.y);
    a[1] = make_float2(m1.x - v1.y, m1.y + v1.x);
    a[2] = make_float2(m2.x - v2.y, m2.y + v2.x);
    a[3] = make_float2(m2.x + v2.y, m2.y - v2.x);
    a[4] = make_float2(m1.x + v1.y, m1.y - v1.x);
}

// Radix-8 DIT with j = 0: constant twiddles.
__device__ __forceinline__ void radix8_dit_j0(cplx x[8]) {
#pragma unroll
    for (int t = 0; t < 8; t += 2) {
        cplx v = x[t + 1];
        x[t + 1] = csub(x[t], v);
        x[t]     = cadd(x[t], v);
    }
#pragma unroll
    for (int b0 = 0; b0 < 8; b0 += 4) {
        {
            cplx v = x[b0 + 2];
            x[b0 + 2] = csub(x[b0], v);
            x[b0]     = cadd(x[b0], v);
        }
        {
            cplx v = mul_negi(x[b0 + 3]);
            x[b0 + 3] = csub(x[b0 + 1], v);
            x[b0 + 1] = cadd(x[b0 + 1], v);
        }
    }
    {
        cplx v = x[4];
        x[4] = csub(x[0], v); x[0] = cadd(x[0], v);
    }
    {
        cplx h = x[5];
        cplx v = make_float2(RHALF * (h.x + h.y), RHALF * (h.y - h.x));
        x[5] = csub(x[1], v); x[1] = cadd(x[1], v);
    }
    {
        cplx v = mul_negi(x[6]);
        x[6] = csub(x[2], v); x[2] = cadd(x[2], v);
    }
    {
        cplx h = x[7];
        cplx v = make_float2(RHALF * (h.y - h.x), -RHALF * (h.x + h.y));
        x[7] = csub(x[3], v); x[3] = cadd(x[3], v);
    }
}

// Radix-8 DIF with j = 0 (inverse, conj twiddles).
__device__ __forceinline__ void radix8_dif_j0(cplx x[8]) {
    {
        cplx u = x[0], v = x[4];
        x[0] = cadd(u, v); x[4] = csub(u, v);
    }
    {
        cplx u = x[1], v = x[5];
        x[1] = cadd(u, v);
        cplx d = csub(u, v);
        x[5] = make_float2(RHALF * (d.x - d.y), RHALF * (d.x + d.y));
    }
    {
        cplx u = x[2], v = x[6];
        x[2] = cadd(u, v);
        x[6] = mul_posi(csub(u, v));
    }
    {
        cplx u = x[3], v = x[7];
        x[3] = cadd(u, v);
        cplx d = csub(u, v);
        x[7] = make_float2(-RHALF * (d.x + d.y), RHALF * (d.x - d.y));
    }
#pragma unroll
    for (int b0 = 0; b0 < 8; b0 += 4) {
        {
            cplx u = x[b0], v = x[b0 + 2];
            x[b0]     = cadd(u, v);
            x[b0 + 2] = csub(u, v);
        }
        {
            cplx u = x[b0 + 1], v = x[b0 + 3];
            x[b0 + 1] = cadd(u, v);
            x[b0 + 3] = mul_posi(csub(u, v));
        }
    }
#pragma unroll
    for (int t = 0; t < 8; t += 2) {
        cplx u = x[t], v = x[t + 1];
        x[t]     = cadd(u, v);
        x[t + 1] = csub(u, v);
    }
}

// Radix-16 DIT: radix-2 stages 3..6 on x[t] = row (j + 8t), j in [0,8).
__device__ __forceinline__ void radix16_dit(cplx x[16], int j, const cplx* t128) {
    cplx wa = t128[8 * j];
#pragma unroll
    for (int t = 0; t < 16; t += 2) {
        cplx v = cmul(x[t + 1], wa);
        x[t + 1] = csub(x[t], v);
        x[t]     = cadd(x[t], v);
    }
    cplx wb0 = t128[4 * j];
    cplx wb1 = t128[4 * j + 32];
#pragma unroll
    for (int b0 = 0; b0 < 16; b0 += 4) {
        {
            cplx v = cmul(x[b0 + 2], wb0);
            x[b0 + 2] = csub(x[b0], v);
            x[b0]     = cadd(x[b0], v);
        }
        {
            cplx v = cmul(x[b0 + 3], wb1);
            x[b0 + 3] = csub(x[b0 + 1], v);
            x[b0 + 1] = cadd(x[b0 + 1], v);
        }
    }
#pragma unroll
    for (int grp = 0; grp < 16; grp += 8) {
#pragma unroll
        for (int q = 0; q < 4; q++) {
            cplx w = t128[2 * j + 16 * q];
            cplx v = cmul(x[grp + q + 4], w);
            x[grp + q + 4] = csub(x[grp + q], v);
            x[grp + q]     = cadd(x[grp + q], v);
        }
    }
#pragma unroll
    for (int t = 0; t < 8; t++) {
        cplx w = t128[j + 8 * t];
        cplx v = cmul(x[t + 8], w);
        x[t + 8] = csub(x[t], v);
        x[t]     = cadd(x[t], v);
    }
}

// Radix-16 DIF: inverse stages 6..3 with conj twiddles.
__device__ __forceinline__ void radix16_dif(cplx x[16], int j, const cplx* t128) {
#pragma unroll
    for (int t = 0; t < 8; t++) {
        cplx w = t128[j + 8 * t];
        cplx u = x[t], v = x[t + 8];
        x[t]     = cadd(u, v);
        x[t + 8] = cmulc(csub(u, v), w);
    }
#pragma unroll
    for (int grp = 0; grp < 16; grp += 8) {
#pragma unroll
        for (int q = 0; q < 4; q++) {
            cplx w = t128[2 * j + 16 * q];
            cplx u = x[grp + q], v = x[grp + q + 4];
            x[grp + q]     = cadd(u, v);
            x[grp + q + 4] = cmulc(csub(u, v), w);
        }
    }
    cplx wb0 = t128[4 * j];
    cplx wb1 = t128[4 * j + 32];
#pragma unroll
    for (int b0 = 0; b0 < 16; b0 += 4) {
        {
            cplx u = x[b0], v = x[b0 + 2];
            x[b0]     = cadd(u, v);
            x[b0 + 2] = cmulc(csub(u, v), wb0);
        }
        {
            cplx u = x[b0 + 1], v = x[b0 + 3];
            x[b0 + 1] = cadd(u, v);
            x[b0 + 3] = cmulc(csub(u, v), wb1);
        }
    }
    cplx wa = t128[8 * j];
#pragma unroll
    for (int t = 0; t < 16; t += 2) {
        cplx u = x[t], v = x[t + 1];
        x[t]     = cadd(u, v);
        x[t + 1] = cmulc(csub(u, v), wa);
    }
}

// ---------------------------------------------------------------------------
// Kernel 2: z = y1 + i*y2, Z = FFT_16000 (128x125 four-step), Hermitian split
// + pointwise multiply, phi = Re(IFFT)/N.  [verified R10 FFT structure]
// Count-sketch (idx, sgn) recombined inline from the per-half partials.
// ---------------------------------------------------------------------------
__global__ void __launch_bounds__(THREADS)
mcb_fft_kernel(const float* __restrict__ x1, const float* __restrict__ x2,
               float* __restrict__ out) {
    extern __shared__ cplx S[];                // 16000 complex = 128000 B
    __shared__ cplx t128[128];
    __shared__ cplx t125[125];
    __shared__ cplx tS[125];

    const int tid = threadIdx.x;
    const int b   = blockIdx.x;

    if (tid < 128) t128[tid] = g_t128[tid];
    else if (tid < 256) { if (tid - 128 < 125) t125[tid - 128] = g_t125[tid - 128]; }
    else if (tid < 384) { if (tid - 256 < 125) tS[tid - 256]   = g_tS[tid - 256]; }
    for (int i = tid; i < P_DIM; i += THREADS) S[i] = make_float2(0.0f, 0.0f);
    __syncthreads();

    // scatter: y1 -> real, y2 -> imag, rows bit-reversed for the DIT stages
    for (int d = tid; d < D_DIM; d += THREADS) {
        float sg = g_s0[d] + g_s1[d];
        int p = (int)rintf((g_w0[d] + g_w1[d]) * sg);
        float v = x1[b * D_DIM + d] * sg;
        int n1 = p / 125, n2 = p - n1 * 125;
        int r = __brev(n1) >> 25;
        atomicAdd(&S[r * 125 + n2].x, v);
        sg = g_s0[D_DIM + d] + g_s1[D_DIM + d];
        p = (int)rintf((g_w0[D_DIM + d] + g_w1[D_DIM + d]) * sg);
        v = x2[b * D_DIM + d] * sg;
        n1 = p / 125; n2 = p - n1 * 125;
        r = __brev(n1) >> 25;
        atomicAdd(&S[r * 125 + n2].y, v);
    }
    __syncthreads();

    // ---- forward radix-2 stages 0..2 (rows 8g+t, fixed col), j=0 specialized ----
    for (int idx = tid; idx < 2000; idx += THREADS) {
        int c = idx % 125;
        int g = idx / 125;
        int base = g * 1000 + c;
        cplx x[8];
#pragma unroll
        for (int t = 0; t < 8; t++) x[t] = S[base + t * 125];
        radix8_dit_j0(x);
#pragma unroll
        for (int t = 0; t < 8; t++) S[base + t * 125] = x[t];
    }
    __syncthreads();

    // ---- forward radix-2 stages 3..6 + inter-phase twiddle (radix-16) ----
    if (tid < 1000) {
        int c = tid % 125;
        int j = tid / 125;        // 0..7
        int base = j * 125 + c;
        cplx x[16];
#pragma unroll
        for (int t = 0; t < 16; t++) x[t] = S[base + t * 1000];
        radix16_dit(x, j, t128);
#pragma unroll
        for (int t = 0; t < 16; t++) {
            int k1 = j + 8 * t;
            int mm = c * k1;
            int q = mm / 125, rr = mm - q * 125;
            S[base + t * 1000] = cmul(x[t], cmul(t128[q], tS[rr]));
        }
    }
    __syncthreads();

    // ---- forward: 3 radix-5 DIF stages (length-125 row FFTs) ----
#pragma unroll
    for (int sidx = 0; sidx < 3; sidx++) {
        const int L = (sidx == 0) ? 125 : (sidx == 1) ? 25 : 5;
        const int m = L / 5;
        const int f = 125 / L;
        for (int idx = tid; idx < 3200; idx += THREADS) {
            int r  = idx & 127;
            int bj = idx >> 7;
            int j  = bj % m;
            int base = r * 125 + (bj / m) * L + j;
            cplx a[5];
            a[0] = S[base];
            a[1] = S[base + m];
            a[2] = S[base + 2 * m];
            a[3] = S[base + 3 * m];
            a[4] = S[base + 4 * m];
            bf5_fwd(a);
            int jf = j * f;
            S[base]         = a[0];
            S[base + m]     = cmul(a[1], t125[jf]);
            S[base + 2 * m] = cmul(a[2], t125[2 * jf]);
            S[base + 3 * m] = cmul(a[3], t125[3 * jf]);
            S[base + 4 * m] = cmul(a[4], t125[4 * jf]);
        }
        __syncthreads();
    }

    // ---- Hermitian split + pointwise multiply, in scrambled storage ----
    for (int k = tid; k <= 8000; k += THREADS) {
        if (k == 0) {
            cplx z = S[0];
            S[0] = make_float2(z.x * z.y, 0.0f);
        } else if (k == 8000) {
            const int addr = 64 * 125 + 62;
            cplx z = S[addr];
            S[addr] = make_float2(z.x * z.y, 0.0f);
        } else {
            int k1 = k & 127, k2 = k >> 7;
            int pa = k1 * 125 + dr5(k2);
            int kp = P_DIM - k;
            int k1p = kp & 127, k2p = kp >> 7;
            int pb = k1p * 125 + dr5(k2p);
            cplx A = S[pa];
            cplx Bv = S[pb];
            float F1r = 0.5f * (A.x + Bv.x), F1i = 0.5f * (A.y - Bv.y);
            float F2r = 0.5f * (A.y + Bv.y), F2i = 0.5f * (Bv.x - A.x);
            float Hr = F1r * F2r - F1i * F2i;
            float Hi = F1r * F2i + F1i * F2r;
            S[pa] = make_float2(Hr,  Hi);
            S[pb] = make_float2(Hr, -Hi);
        }
    }
    __syncthreads();

    // ---- inverse: 3 radix-5 DIT stages (rows), conj twiddles ----
#pragma unroll
    for (int sidx = 0; sidx < 3; sidx++) {
        const int L = (sidx == 0) ? 5 : (sidx == 1) ? 25 : 125;
        const int m = L / 5;
        const int f = 125 / L;
        for (int idx = tid; idx < 3200; idx += THREADS) {
            int r  = idx & 127;
            int bj = idx >> 7;
            int j  = bj % m;
            int base = r * 125 + (bj / m) * L + j;
            int jf = j * f;
            cplx a[5];
            a[0] = S[base];
            a[1] = cmulc(S[base + m],     t125[jf]);
            a[2] = cmulc(S[base + 2 * m], t125[2 * jf]);
            a[3] = cmulc(S[base + 3 * m], t125[3 * jf]);
            a[4] = cmulc(S[base + 4 * m], t125[4 * jf]);
            bf5_inv(a);
            S[base]         = a[0];
            S[base + m]     = a[1];
            S[base + 2 * m] = a[2];
            S[base + 3 * m] = a[3];
            S[base + 4 * m] = a[4];
        }
        __syncthreads();
    }

    // ---- inverse inter-phase twiddle (conj) + radix-2 stages 6..3 (radix-16) ----
    if (tid < 1000) {
        int c = tid % 125;
        int j = tid / 125;
        int base = j * 125 + c;
        cplx x[16];
#pragma unroll
        for (int t = 0; t < 16; t++) {
            int k1 = j + 8 * t;
            int mm = c * k1;
            int q = mm / 125, rr = mm - q * 125;
            x[t] = cmulc(S[base + t * 1000], cmul(t128[q], tS[rr]));
        }
        radix16_dif(x, j, t128);
#pragma unroll
        for (int t = 0; t < 16; t++) S[base + t * 1000] = x[t];
    }
    __syncthreads();

    // ---- inverse radix-2 stages 2..0 (j=0 specialized), fused with output ----
    const float scale = 1.0f / 16000.0f;
    for (int idx = tid; idx < 2000; idx += THREADS) {
        int c = idx % 125;
        int g = idx / 125;
        int base = g * 1000 + c;
        cplx x[8];
#pragma unroll
        for (int t = 0; t < 8; t++) x[t] = S[base + t * 125];
        radix8_dif_j0(x);
#pragma unroll
        for (int t = 0; t < 8; t++) {
            int n1 = __brev(8 * g + t) >> 25;
            out[b * P_DIM + n1 * 125 + c] = x[t].x * scale;
        }
    }
}

extern "C" void kernel_launch(void* const* d_in, const int* in_sizes, int n_in,
                              void* d_out, int out_size) {
    const float* x1 = (const float*)d_in[0];
    const float* x2 = (const float*)d_in[1];
    const float* C1 = (const float*)d_in[2];
    const float* C2 = (const float*)d_in[3];
    float* out = (float*)d_out;

    extract_kernel<<<4 * D_DIM + 1, EX_THREADS>>>(C1, C2);

    const size_t smem = (size_t)P_DIM * sizeof(cplx);  // 128000 B
    cudaFuncSetAttribute(mcb_fft_kernel,
                         cudaFuncAttributeMaxDynamicSharedMemorySize, (int)smem);
    mcb_fft_kernel<<<B_BATCH, THREADS, smem>>>(x1, x2, out);
}

// round 15
// speedup vs baseline: 1.0306x; 1.0301x over previous
#include <cuda_runtime.h>
#include <math.h>

#define B_BATCH 128
#define D_DIM   2048
#define P_DIM   16000
#define THREADS 1024

// Per-half moment partials: [half][row].  Written unconditionally every
// launch (plain stores, no atomics) -> no zeroing needed, graph-safe.
static __device__ float g_s0[2 * D_DIM], g_s1[2 * D_DIM];
static __device__ float g_w0[2 * D_DIM], g_w1[2 * D_DIM];
static __device__ float2 g_t128[128];
static __device__ float2 g_t125[125];
static __device__ float2 g_tS[125];

// ---------------------------------------------------------------------------
// Kernel 1: moment partial sums over HALF-rows (8192 scan blocks, 256 thr).
// sgn = sum(C[row,:]), idx = sgn * sum(p*C[row,p]); exact in fp32.
// Block 8192 computes the FFT twiddle tables concurrently.
// Triggers the dependent FFT launch at entry (PDL); the FFT's
// cudaGridDependencySynchronize still guarantees full completion.
// ---------------------------------------------------------------------------
#define EX_THREADS 256
#define HALF_F4    2000              // float4s per half-row

__global__ void __launch_bounds__(EX_THREADS)
extract_kernel(const float* __restrict__ C1, const float* __restrict__ C2) {
    cudaTriggerProgrammaticLaunchCompletion();
    const int tid = threadIdx.x;
    if (blockIdx.x == 4 * D_DIM) {   // twiddle block
        const double TWO_PI = 6.283185307179586476925286766559;
        for (int t = tid; t < 128; t += EX_THREADS) {
            double s, c; sincos(-TWO_PI * (double)t / 128.0, &s, &c);
            g_t128[t] = make_float2((float)c, (float)s);
        }
        for (int t = tid; t < 125; t += EX_THREADS) {
            double s, c;
            sincos(-TWO_PI * (double)t / 125.0, &s, &c);
            g_t125[t] = make_float2((float)c, (float)s);
            sincos(-TWO_PI * (double)t / 16000.0, &s, &c);
            g_tS[t] = make_float2((float)c, (float)s);
        }
        return;
    }
    const int row  = blockIdx.x >> 1;        // 0..4095
    const int half = blockIdx.x & 1;
    const float4* b4 = (const float4*)((row < D_DIM)
                        ? (C1 + (size_t)row * P_DIM)
                        : (C2 + (size_t)(row - D_DIM) * P_DIM));
    b4 += half * HALF_F4;
    float4 v[8];
#pragma unroll
    for (int k = 0; k < 8; k++) {
        int i = k * EX_THREADS + tid;
        v[k] = (i < HALF_F4) ? b4[i] : make_float4(0.0f, 0.0f, 0.0f, 0.0f);
    }
    float s = 0.0f, w = 0.0f;
#pragma unroll
    for (int k = 0; k < 8; k++) {
        int i = k * EX_THREADS + tid;
        float p0 = (float)(4 * (half * HALF_F4 + i));
        float sv = (v[k].x + v[k].y) + (v[k].z + v[k].w);
        s += sv;
        w += p0 * sv + (v[k].y + 2.0f * v[k].z + 3.0f * v[k].w);
    }
#pragma unroll
    for (int o = 16; o > 0; o >>= 1) {
        s += __shfl_down_sync(0xFFFFFFFFu, s, o);
        w += __shfl_down_sync(0xFFFFFFFFu, w, o);
    }
    __shared__ float ss[EX_THREADS / 32], sw[EX_THREADS / 32];
    int lane = tid & 31, warp = tid >> 5;
    if (lane == 0) { ss[warp] = s; sw[warp] = w; }
    __syncthreads();
    if (warp == 0) {
        s = (lane < EX_THREADS / 32) ? ss[lane] : 0.0f;
        w = (lane < EX_THREADS / 32) ? sw[lane] : 0.0f;
#pragma unroll
        for (int o = EX_THREADS / 64; o > 0; o >>= 1) {
            s += __shfl_down_sync(0xFFFFFFFFu, s, o);
            w += __shfl_down_sync(0xFFFFFFFFu, w, o);
        }
        if (lane == 0) {
            if (half == 0) { g_s0[row] = s; g_w0[row] = w; }
            else           { g_s1[row] = s; g_w1[row] = w; }
        }
    }
}

// base-5 digit reversal of 3 digits (involution), x in [0,125)
__device__ __forceinline__ int dr5(int x) {
    int a = x / 25;
    int rem = x - 25 * a;
    int b = rem / 5;
    int c = rem - 5 * b;
    return c * 25 + b * 5 + a;
}

typedef float2 cplx;
__device__ __forceinline__ cplx cmul(cplx a, cplx b) {
    return make_float2(a.x * b.x - a.y * b.y, a.x * b.y + a.y * b.x);
}
__device__ __forceinline__ cplx cmulc(cplx a, cplx b) {   // a * conj(b)
    return make_float2(a.x * b.x + a.y * b.y, a.y * b.x - a.x * b.y);
}
__device__ __forceinline__ cplx cadd(cplx a, cplx b) { return make_float2(a.x + b.x, a.y + b.y); }
__device__ __forceinline__ cplx csub(cplx a, cplx b) { return make_float2(a.x - b.x, a.y - b.y); }
__device__ __forceinline__ cplx mul_negi(cplx v) { return make_float2(v.y, -v.x); }   // v * (-i)
__device__ __forceinline__ cplx mul_posi(cplx v) { return make_float2(-v.y, v.x); }   // v * (+i)

#define RHALF 0.70710678118654752f
#define C72  ( 0.30901699437494742f)
#define S72  ( 0.95105651629515357f)
#define C144 (-0.80901699437494745f)
#define S144 ( 0.58778525229247314f)

// 5-point butterflies, in place, no twiddle.
__device__ __forceinline__ void bf5_fwd(cplx a[5]) {
    cplx t1 = cadd(a[1], a[4]), t3 = csub(a[1], a[4]);
    cplx t2 = cadd(a[2], a[3]), t4 = csub(a[2], a[3]);
    cplx a0 = a[0];
    cplx m1 = make_float2(a0.x + C72 * t1.x + C144 * t2.x, a0.y + C72 * t1.y + C144 * t2.y);
    cplx m2 = make_float2(a0.x + C144 * t1.x + C72 * t2.x, a0.y + C144 * t1.y + C72 * t2.y);
    cplx v1 = make_float2(S72 * t3.x + S144 * t4.x, S72 * t3.y + S144 * t4.y);
    cplx v2 = make_float2(S144 * t3.x - S72 * t4.x, S144 * t3.y - S72 * t4.y);
    a[0] = make_float2(a0.x + t1.x + t2.x, a0.y + t1.y + t2.y);
    a[1] = make_float2(m1.x + v1.y, m1.y - v1.x);
    a[2] = make_float2(m2.x + v2.y, m2.y - v2.x);
    a[3] = make_float2(m2.x - v2.y, m2.y + v2.x);
    a[4] = make_float2(m1.x - v1.y, m1.y + v1.x);
}
__device__ __forceinline__ void bf5_inv(cplx a[5]) {
    cplx t1 = cadd(a[1], a[4]), t3 = csub(a[1], a[4]);
    cplx t2 = cadd(a[2], a[3]), t4 = csub(a[2], a[3]);
    cplx a0 = a[0];
    cplx m1 = make_float2(a0.x + C72 * t1.x + C144 * t2.x, a0.y + C72 * t1.y + C144 * t2.y);
    cplx m2 = make_float2(a0.x + C144 * t1.x + C72 * t2.x, a0.y + C144 * t1.y + C72 * t2.y);
    cplx v1 = make_float2(S72 * t3.x + S144 * t4.x, S72 * t3.y + S144 * t4.y);
    cplx v2 = make_float2(S144 * t3.x - S72 * t4.x, S144 * t3.y - S72 * t4.y);
    a[0] = make_float2(a0.x + t1.x + t2.x, a0.y + t1.y + t2.y);
    a[1] = make_float2(m1.x - v1.y, m1.y + v1.x);
    a[2] = make_float2(m2.x - v2.y, m2.y + v2.x);
    a[3] = make_float2(m2.x + v2.y, m2.y - v2.x);
    a[4] = make_float2(m1.x + v1.y, m1.y - v1.x);
}

// Radix-8 DIT with j = 0: constant twiddles.
__device__ __forceinline__ void radix8_dit_j0(cplx x[8]) {
#pragma unroll
    for (int t = 0; t < 8; t += 2) {
        cplx v = x[t + 1];
        x[t + 1] = csub(x[t], v);
        x[t]     = cadd(x[t], v);
    }
#pragma unroll
    for (int b0 = 0; b0 < 8; b0 += 4) {
        {
            cplx v = x[b0 + 2];
            x[b0 + 2] = csub(x[b0], v);
            x[b0]     = cadd(x[b0], v);
        }
        {
            cplx v = mul_negi(x[b0 + 3]);
            x[b0 + 3] = csub(x[b0 + 1], v);
            x[b0 + 1] = cadd(x[b0 + 1], v);
        }
    }
    {
        cplx v = x[4];
        x[4] = csub(x[0], v); x[0] = cadd(x[0], v);
    }
    {
        cplx h = x[5];
        cplx v = make_float2(RHALF * (h.x + h.y), RHALF * (h.y - h.x));
        x[5] = csub(x[1], v); x[1] = cadd(x[1], v);
    }
    {
        cplx v = mul_negi(x[6]);
        x[6] = csub(x[2], v); x[2] = cadd(x[2], v);
    }
    {
        cplx h = x[7];
        cplx v = make_float2(RHALF * (h.y - h.x), -RHALF * (h.x + h.y));
        x[7] = csub(x[3], v); x[3] = cadd(x[3], v);
    }
}

// Radix-8 DIF with j = 0 (inverse, conj twiddles).
__device__ __forceinline__ void radix8_dif_j0(cplx x[8]) {
    {
        cplx u = x[0], v = x[4];
        x[0] = cadd(u, v); x[4] = csub(u, v);
    }
    {
        cplx u = x[1], v = x[5];
        x[1] = cadd(u, v);
        cplx d = csub(u, v);
        x[5] = make_float2(RHALF * (d.x - d.y), RHALF * (d.x + d.y));
    }
    {
        cplx u = x[2], v = x[6];
        x[2] = cadd(u, v);
        x[6] = mul_posi(csub(u, v));
    }
    {
        cplx u = x[3], v = x[7];
        x[3] = cadd(u, v);
        cplx d = csub(u, v);
        x[7] = make_float2(-RHALF * (d.x + d.y), RHALF * (d.x - d.y));
    }
#pragma unroll
    for (int b0 = 0; b0 < 8; b0 += 4) {
        {
            cplx u = x[b0], v = x[b0 + 2];
            x[b0]     = cadd(u, v);
            x[b0 + 2] = csub(u, v);
        }
        {
            cplx u = x[b0 + 1], v = x[b0 + 3];
            x[b0 + 1] = cadd(u, v);
            x[b0 + 3] = mul_posi(csub(u, v));
        }
    }
#pragma unroll
    for (int t = 0; t < 8; t += 2) {
        cplx u = x[t], v = x[t + 1];
        x[t]     = cadd(u, v);
        x[t + 1] = csub(u, v);
    }
}

// Radix-16 DIT: radix-2 stages 3..6 on x[t] = row (j + 8t), j in [0,8).
__device__ __forceinline__ void radix16_dit(cplx x[16], int j, const cplx* t128) {
    cplx wa = t128[8 * j];
#pragma unroll
    for (int t = 0; t < 16; t += 2) {
        cplx v = cmul(x[t + 1], wa);
        x[t + 1] = csub(x[t], v);
        x[t]     = cadd(x[t], v);
    }
    cplx wb0 = t128[4 * j];
    cplx wb1 = t128[4 * j + 32];
#pragma unroll
    for (int b0 = 0; b0 < 16; b0 += 4) {
        {
            cplx v = cmul(x[b0 + 2], wb0);
            x[b0 + 2] = csub(x[b0], v);
            x[b0]     = cadd(x[b0], v);
        }
        {
            cplx v = cmul(x[b0 + 3], wb1);
            x[b0 + 3] = csub(x[b0 + 1], v);
            x[b0 + 1] = cadd(x[b0 + 1], v);
        }
    }
#pragma unroll
    for (int grp = 0; grp < 16; grp += 8) {
#pragma unroll
        for (int q = 0; q < 4; q++) {
            cplx w = t128[2 * j + 16 * q];
            cplx v = cmul(x[grp + q + 4], w);
            x[grp + q + 4] = csub(x[grp + q], v);
            x[grp + q]     = cadd(x[grp + q], v);
        }
    }
#pragma unroll
    for (int t = 0; t < 8; t++) {
        cplx w = t128[j + 8 * t];
        cplx v = cmul(x[t + 8], w);
        x[t + 8] = csub(x[t], v);
        x[t]     = cadd(x[t], v);
    }
}

// Radix-16 DIF: inverse stages 6..3 with conj twiddles.
__device__ __forceinline__ void radix16_dif(cplx x[16], int j, const cplx* t128) {
#pragma unroll
    for (int t = 0; t < 8; t++) {
        cplx w = t128[j + 8 * t];
        cplx u = x[t], v = x[t + 8];
        x[t]     = cadd(u, v);
        x[t + 8] = cmulc(csub(u, v), w);
    }
#pragma unroll
    for (int grp = 0; grp < 16; grp += 8) {
#pragma unroll
        for (int q = 0; q < 4; q++) {
            cplx w = t128[2 * j + 16 * q];
            cplx u = x[grp + q], v = x[grp + q + 4];
            x[grp + q]     = cadd(u, v);
            x[grp + q + 4] = cmulc(csub(u, v), w);
        }
    }
    cplx wb0 = t128[4 * j];
    cplx wb1 = t128[4 * j + 32];
#pragma unroll
    for (int b0 = 0; b0 < 16; b0 += 4) {
        {
            cplx u = x[b0], v = x[b0 + 2];
            x[b0]     = cadd(u, v);
            x[b0 + 2] = cmulc(csub(u, v), wb0);
        }
        {
            cplx u = x[b0 + 1], v = x[b0 + 3];
            x[b0 + 1] = cadd(u, v);
            x[b0 + 3] = cmulc(csub(u, v), wb1);
        }
    }
    cplx wa = t128[8 * j];
#pragma unroll
    for (int t = 0; t < 16; t += 2) {
        cplx u = x[t], v = x[t + 1];
        x[t]     = cadd(u, v);
        x[t + 1] = cmulc(csub(u, v), wa);
    }
}

// ---------------------------------------------------------------------------
// Kernel 2: z = y1 + i*y2, Z = FFT_16000 (128x125 four-step), Hermitian split
// + pointwise multiply, phi = Re(IFFT)/N.  [verified R10 FFT structure]
// PDL: zero the smem line BEFORE the grid dependency resolves, then sync.
// ---------------------------------------------------------------------------
__global__ void __launch_bounds__(THREADS)
mcb_fft_kernel(const float* __restrict__ x1, const float* __restrict__ x2,
               float* __restrict__ out) {
    extern __shared__ cplx S[];                // 16000 complex = 128000 B
    __shared__ cplx t128[128];
    __shared__ cplx t125[125];
    __shared__ cplx tS[125];

    const int tid = threadIdx.x;
    const int b   = blockIdx.x;

    // Pre-dependency work: zero the shared line (independent of extract).
    for (int i = tid; i < P_DIM; i += THREADS) S[i] = make_float2(0.0f, 0.0f);

    // Wait for the extract kernel's results (moments + twiddle tables).
    cudaGridDependencySynchronize();

    if (tid < 128) t128[tid] = g_t128[tid];
    else if (tid < 256) { if (tid - 128 < 125) t125[tid - 128] = g_t125[tid - 128]; }
    else if (tid < 384) { if (tid - 256 < 125) tS[tid - 256]   = g_tS[tid - 256]; }
    __syncthreads();

    // scatter: y1 -> real, y2 -> imag, rows bit-reversed for the DIT stages
    for (int d = tid; d < D_DIM; d += THREADS) {
        float sg = g_s0[d] + g_s1[d];
        int p = (int)rintf((g_w0[d] + g_w1[d]) * sg);
        float v = x1[b * D_DIM + d] * sg;
        int n1 = p / 125, n2 = p - n1 * 125;
        int r = __brev(n1) >> 25;
        atomicAdd(&S[r * 125 + n2].x, v);
        sg = g_s0[D_DIM + d] + g_s1[D_DIM + d];
        p = (int)rintf((g_w0[D_DIM + d] + g_w1[D_DIM + d]) * sg);
        v = x2[b * D_DIM + d] * sg;
        n1 = p / 125; n2 = p - n1 * 125;
        r = __brev(n1) >> 25;
        atomicAdd(&S[r * 125 + n2].y, v);
    }
    __syncthreads();

    // ---- forward radix-2 stages 0..2 (rows 8g+t, fixed col), j=0 specialized ----
    for (int idx = tid; idx < 2000; idx += THREADS) {
        int c = idx % 125;
        int g = idx / 125;
        int base = g * 1000 + c;
        cplx x[8];
#pragma unroll
        for (int t = 0; t < 8; t++) x[t] = S[base + t * 125];
        radix8_dit_j0(x);
#pragma unroll
        for (int t = 0; t < 8; t++) S[base + t * 125] = x[t];
    }
    __syncthreads();

    // ---- forward radix-2 stages 3..6 + inter-phase twiddle (radix-16) ----
    if (tid < 1000) {
        int c = tid % 125;
        int j = tid / 125;        // 0..7
        int base = j * 125 + c;
        cplx x[16];
#pragma unroll
        for (int t = 0; t < 16; t++) x[t] = S[base + t * 1000];
        radix16_dit(x, j, t128);
#pragma unroll
        for (int t = 0; t < 16; t++) {
            int k1 = j + 8 * t;
            int mm = c * k1;
            int q = mm / 125, rr = mm - q * 125;
            S[base + t * 1000] = cmul(x[t], cmul(t128[q], tS[rr]));
        }
    }
    __syncthreads();

    // ---- forward: 3 radix-5 DIF stages (length-125 row FFTs) ----
#pragma unroll
    for (int sidx = 0; sidx < 3; sidx++) {
        const int L = (sidx == 0) ? 125 : (sidx == 1) ? 25 : 5;
        const int m = L / 5;
        const int f = 125 / L;
        for (int idx = tid; idx < 3200; idx += THREADS) {
            int r  = idx & 127;
            int bj = idx >> 7;
            int j  = bj % m;
            int base = r * 125 + (bj / m) * L + j;
            cplx a[5];
            a[0] = S[base];
            a[1] = S[base + m];
            a[2] = S[base + 2 * m];
            a[3] = S[base + 3 * m];
            a[4] = S[base + 4 * m];
            bf5_fwd(a);
            int jf = j * f;
            S[base]         = a[0];
            S[base + m]     = cmul(a[1], t125[jf]);
            S[base + 2 * m] = cmul(a[2], t125[2 * jf]);
            S[base + 3 * m] = cmul(a[3], t125[3 * jf]);
            S[base + 4 * m] = cmul(a[4], t125[4 * jf]);
        }
        __syncthreads();
    }

    // ---- Hermitian split + pointwise multiply, in scrambled storage ----
    for (int k = tid; k <= 8000; k += THREADS) {
        if (k == 0) {
            cplx z = S[0];
            S[0] = make_float2(z.x * z.y, 0.0f);
        } else if (k == 8000) {
            const int addr = 64 * 125 + 62;
            cplx z = S[addr];
            S[addr] = make_float2(z.x * z.y, 0.0f);
        } else {
            int k1 = k & 127, k2 = k >> 7;
            int pa = k1 * 125 + dr5(k2);
            int kp = P_DIM - k;
            int k1p = kp & 127, k2p = kp >> 7;
            int pb = k1p * 125 + dr5(k2p);
            cplx A = S[pa];
            cplx Bv = S[pb];
            float F1r = 0.5f * (A.x + Bv.x), F1i = 0.5f * (A.y - Bv.y);
            float F2r = 0.5f * (A.y + Bv.y), F2i = 0.5f * (Bv.x - A.x);
            float Hr = F1r * F2r - F1i * F2i;
            float Hi = F1r * F2i + F1i * F2r;
            S[pa] = make_float2(Hr,  Hi);
            S[pb] = make_float2(Hr, -Hi);
        }
    }
    __syncthreads();

    // ---- inverse: 3 radix-5 DIT stages (rows), conj twiddles ----
#pragma unroll
    for (int sidx = 0; sidx < 3; sidx++) {
        const int L = (sidx == 0) ? 5 : (sidx == 1) ? 25 : 125;
        const int m = L / 5;
        const int f = 125 / L;
        for (int idx = tid; idx < 3200; idx += THREADS) {
            int r  = idx & 127;
            int bj = idx >> 7;
            int j  = bj % m;
            int base = r * 125 + (bj / m) * L + j;
            int jf = j * f;
            cplx a[5];
            a[0] = S[base];
            a[1] = cmulc(S[base + m],     t125[jf]);
            a[2] = cmulc(S[base + 2 * m], t125[2 * jf]);
            a[3] = cmulc(S[base + 3 * m], t125[3 * jf]);
            a[4] = cmulc(S[base + 4 * m], t125[4 * jf]);
            bf5_inv(a);
            S[base]         = a[0];
            S[base + m]     = a[1];
            S[base + 2 * m] = a[2];
            S[base + 3 * m] = a[3];
            S[base + 4 * m] = a[4];
        }
        __syncthreads();
    }

    // ---- inverse inter-phase twiddle (conj) + radix-2 stages 6..3 (radix-16) ----
    if (tid < 1000) {
        int c = tid % 125;
        int j = tid / 125;
        int base = j * 125 + c;
        cplx x[16];
#pragma unroll
        for (int t = 0; t < 16; t++) {
            int k1 = j + 8 * t;
            int mm = c * k1;
            int q = mm / 125, rr = mm - q * 125;
            x[t] = cmulc(S[base + t * 1000], cmul(t128[q], tS[rr]));
        }
        radix16_dif(x, j, t128);
#pragma unroll
        for (int t = 0; t < 16; t++) S[base + t * 1000] = x[t];
    }
    __syncthreads();

    // ---- inverse radix-2 stages 2..0 (j=0 specialized), fused with output ----
    const float scale = 1.0f / 16000.0f;
    for (int idx = tid; idx < 2000; idx += THREADS) {
        int c = idx % 125;
        int g = idx / 125;
        int base = g * 1000 + c;
        cplx x[8];
#pragma unroll
        for (int t = 0; t < 8; t++) x[t] = S[base + t * 125];
        radix8_dif_j0(x);
#pragma unroll
        for (int t = 0; t < 8; t++) {
            int n1 = __brev(8 * g + t) >> 25;
            out[b * P_DIM + n1 * 125 + c] = x[t].x * scale;
        }
    }
}

extern "C" void kernel_launch(void* const* d_in, const int* in_sizes, int n_in,
                              void* d_out, int out_size) {
    const float* x1 = (const float*)d_in[0];
    const float* x2 = (const float*)d_in[1];
    const float* C1 = (const float*)d_in[2];
    const float* C2 = (const float*)d_in[3];
    float* out = (float*)d_out;

    extract_kernel<<<4 * D_DIM + 1, EX_THREADS>>>(C1, C2);

    const size_t smem = (size_t)P_DIM * sizeof(cplx);  // 128000 B
    cudaFuncSetAttribute(mcb_fft_kernel,
                         cudaFuncAttributeMaxDynamicSharedMemorySize, (int)smem);

    // PDL launch: FFT may begin (smem zeroing) while extract drains.
    cudaLaunchConfig_t cfg = {};
    cfg.gridDim  = dim3(B_BATCH, 1, 1);
    cfg.blockDim = dim3(THREADS, 1, 1);
    cfg.dynamicSmemBytes = smem;
    cfg.stream = 0;
    cudaLaunchAttribute attrs[1];
    attrs[0].id = cudaLaunchAttributeProgrammaticStreamSerialization;
    attrs[0].val.programmaticStreamSerializationAllowed = 1;
    cfg.attrs = attrs;
    cfg.numAttrs = 1;
    cudaError_t err = cudaLaunchKernelEx(&cfg, mcb_fft_kernel, x1, x2, out);
    if (err != cudaSuccess) {
        // Fallback: plain launch (cudaGridDependencySynchronize is a no-op).
        mcb_fft_kernel<<<B_BATCH, THREADS, smem>>>(x1, x2, out);
    }
}

// round 16
// speedup vs baseline: 1.2569x; 1.2196x over previous
#include <cuda_runtime.h>
#include <math.h>

#define B_BATCH 128
#define D_DIM   2048
#define P_DIM   16000
#define THREADS 1024

static __device__ int    g_idx[2 * D_DIM];
static __device__ float  g_sgn[2 * D_DIM];
static __device__ float2 g_t128[128];
static __device__ float2 g_t125[125];
static __device__ float2 g_tS[125];

// ---------------------------------------------------------------------------
// Kernel 1: find the single nonzero (+/-1) per row with a warp-autonomous
// early-exit scan.  One block per row, 8 warps x 500-float4 segments.
// No barriers in the scan loop: warps poll a volatile shared flag.
// Expected bytes read ~55-60% of the matrix.  Block 4096 = twiddle tables.
// ---------------------------------------------------------------------------
#define EX_THREADS 256

__global__ void __launch_bounds__(EX_THREADS)
extract_kernel(const float* __restrict__ C1, const float* __restrict__ C2) {
    cudaTriggerProgrammaticLaunchCompletion();
    const int tid = threadIdx.x;
    if (blockIdx.x == 2 * D_DIM) {   // twiddle block
        const double TWO_PI = 6.283185307179586476925286766559;
        for (int t = tid; t < 128; t += EX_THREADS) {
            double s, c; sincos(-TWO_PI * (double)t / 128.0, &s, &c);
            g_t128[t] = make_float2((float)c, (float)s);
        }
        for (int t = tid; t < 125; t += EX_THREADS) {
            double s, c;
            sincos(-TWO_PI * (double)t / 125.0, &s, &c);
            g_t125[t] = make_float2((float)c, (float)s);
            sincos(-TWO_PI * (double)t / 16000.0, &s, &c);
            g_tS[t] = make_float2((float)c, (float)s);
        }
        return;
    }
    const int row = blockIdx.x;      // 0..4095
    const float4* b4 = (const float4*)((row < D_DIM)
                        ? (C1 + (size_t)row * P_DIM)
                        : (C2 + (size_t)(row - D_DIM) * P_DIM));
    __shared__ volatile int flag;
    if (tid == 0) flag = 0;
    __syncthreads();

    const int warp = tid >> 5, lane = tid & 31;
    const int seg = warp * 500;      // 8 warps x 500 f4 = 4000 f4 = full row

    for (int it = 0; it < 8; it++) {
        if (flag) break;             // volatile poll, no barrier
        int o0 = it * 64 + lane;     // 0..511 range, bounds vs 500
        int o1 = o0 + 32;
        float4 a = (o0 < 500) ? b4[seg + o0] : make_float4(0.f, 0.f, 0.f, 0.f);
        float4 c = (o1 < 500) ? b4[seg + o1] : make_float4(0.f, 0.f, 0.f, 0.f);
        bool hit = (a.x != 0.f) | (a.y != 0.f) | (a.z != 0.f) | (a.w != 0.f) |
                   (c.x != 0.f) | (c.y != 0.f) | (c.z != 0.f) | (c.w != 0.f);
        unsigned m = __ballot_sync(0xFFFFFFFFu, hit);
        if (m) {
            if (hit) {
                int   idx; float sg;
                int p0 = 4 * (seg + o0), p1 = 4 * (seg + o1);
                if      (a.x != 0.f) { idx = p0 + 0; sg = a.x; }
                else if (a.y != 0.f) { idx = p0 + 1; sg = a.y; }
                else if (a.z != 0.f) { idx = p0 + 2; sg = a.z; }
                else if (a.w != 0.f) { idx = p0 + 3; sg = a.w; }
                else if (c.x != 0.f) { idx = p1 + 0; sg = c.x; }
                else if (c.y != 0.f) { idx = p1 + 1; sg = c.y; }
                else if (c.z != 0.f) { idx = p1 + 2; sg = c.z; }
                else                 { idx = p1 + 3; sg = c.w; }
                g_idx[row] = idx;
                g_sgn[row] = sg;
                flag = 1;
            }
            break;
        }
    }
}

// base-5 digit reversal of 3 digits (involution), x in [0,125)
__device__ __forceinline__ int dr5(int x) {
    int a = x / 25;
    int rem = x - 25 * a;
    int b = rem / 5;
    int c = rem - 5 * b;
    return c * 25 + b * 5 + a;
}

typedef float2 cplx;
__device__ __forceinline__ cplx cmul(cplx a, cplx b) {
    return make_float2(a.x * b.x - a.y * b.y, a.x * b.y + a.y * b.x);
}
__device__ __forceinline__ cplx cmulc(cplx a, cplx b) {   // a * conj(b)
    return make_float2(a.x * b.x + a.y * b.y, a.y * b.x - a.x * b.y);
}
__device__ __forceinline__ cplx cadd(cplx a, cplx b) { return make_float2(a.x + b.x, a.y + b.y); }
__device__ __forceinline__ cplx csub(cplx a, cplx b) { return make_float2(a.x - b.x, a.y - b.y); }
__device__ __forceinline__ cplx mul_negi(cplx v) { return make_float2(v.y, -v.x); }   // v * (-i)
__device__ __forceinline__ cplx mul_posi(cplx v) { return make_float2(-v.y, v.x); }   // v * (+i)

#define RHALF 0.70710678118654752f
#define C72  ( 0.30901699437494742f)
#define S72  ( 0.95105651629515357f)
#define C144 (-0.80901699437494745f)
#define S144 ( 0.58778525229247314f)

// 5-point butterflies, in place, no twiddle.
__device__ __forceinline__ void bf5_fwd(cplx a[5]) {
    cplx t1 = cadd(a[1], a[4]), t3 = csub(a[1], a[4]);
    cplx t2 = cadd(a[2], a[3]), t4 = csub(a[2], a[3]);
    cplx a0 = a[0];
    cplx m1 = make_float2(a0.x + C72 * t1.x + C144 * t2.x, a0.y + C72 * t1.y + C144 * t2.y);
    cplx m2 = make_float2(a0.x + C144 * t1.x + C72 * t2.x, a0.y + C144 * t1.y + C72 * t2.y);
    cplx v1 = make_float2(S72 * t3.x + S144 * t4.x, S72 * t3.y + S144 * t4.y);
    cplx v2 = make_float2(S144 * t3.x - S72 * t4.x, S144 * t3.y - S72 * t4.y);
    a[0] = make_float2(a0.x + t1.x + t2.x, a0.y + t1.y + t2.y);
    a[1] = make_float2(m1.x + v1.y, m1.y - v1.x);
    a[2] = make_float2(m2.x + v2.y, m2.y - v2.x);
    a[3] = make_float2(m2.x - v2.y, m2.y + v2.x);
    a[4] = make_float2(m1.x - v1.y, m1.y + v1.x);
}
__device__ __forceinline__ void bf5_inv(cplx a[5]) {
    cplx t1 = cadd(a[1], a[4]), t3 = csub(a[1], a[4]);
    cplx t2 = cadd(a[2], a[3]), t4 = csub(a[2], a[3]);
    cplx a0 = a[0];
    cplx m1 = make_float2(a0.x + C72 * t1.x + C144 * t2.x, a0.y + C72 * t1.y + C144 * t2.y);
    cplx m2 = make_float2(a0.x + C144 * t1.x + C72 * t2.x, a0.y + C144 * t1.y + C72 * t2.y);
    cplx v1 = make_float2(S72 * t3.x + S144 * t4.x, S72 * t3.y + S144 * t4.y);
    cplx v2 = make_float2(S144 * t3.x - S72 * t4.x, S144 * t3.y - S72 * t4.y);
    a[0] = make_float2(a0.x + t1.x + t2.x, a0.y + t1.y + t2.y);
    a[1] = make_float2(m1.x - v1.y, m1.y + v1.x);
    a[2] = make_float2(m2.x - v2.y, m2.y + v2.x);
    a[3] = make_float2(m2.x + v2.y, m2.y - v2.x);
    a[4] = make_float2(m1.x + v1.y, m1.y - v1.x);
}

// Radix-8 DIT with j = 0: constant twiddles.
__device__ __forceinline__ void radix8_dit_j0(cplx x[8]) {
#pragma unroll
    for (int t = 0; t < 8; t += 2) {
        cplx v = x[t + 1];
        x[t + 1] = csub(x[t], v);
        x[t]     = cadd(x[t], v);
    }
#pragma unroll
    for (int b0 = 0; b0 < 8; b0 += 4) {
        {
            cplx v = x[b0 + 2];
            x[b0 + 2] = csub(x[b0], v);
            x[b0]     = cadd(x[b0], v);
        }
        {
            cplx v = mul_negi(x[b0 + 3]);
            x[b0 + 3] = csub(x[b0 + 1], v);
            x[b0 + 1] = cadd(x[b0 + 1], v);
        }
    }
    {
        cplx v = x[4];
        x[4] = csub(x[0], v); x[0] = cadd(x[0], v);
    }
    {
        cplx h = x[5];
        cplx v = make_float2(RHALF * (h.x + h.y), RHALF * (h.y - h.x));
        x[5] = csub(x[1], v); x[1] = cadd(x[1], v);
    }
    {
        cplx v = mul_negi(x[6]);
        x[6] = csub(x[2], v); x[2] = cadd(x[2], v);
    }
    {
        cplx h = x[7];
        cplx v = make_float2(RHALF * (h.y - h.x), -RHALF * (h.x + h.y));
        x[7] = csub(x[3], v); x[3] = cadd(x[3], v);
    }
}

// Radix-8 DIF with j = 0 (inverse, conj twiddles).
__device__ __forceinline__ void radix8_dif_j0(cplx x[8]) {
    {
        cplx u = x[0], v = x[4];
        x[0] = cadd(u, v); x[4] = csub(u, v);
    }
    {
        cplx u = x[1], v = x[5];
        x[1] = cadd(u, v);
        cplx d = csub(u, v);
        x[5] = make_float2(RHALF * (d.x - d.y), RHALF * (d.x + d.y));
    }
    {
        cplx u = x[2], v = x[6];
        x[2] = cadd(u, v);
        x[6] = mul_posi(csub(u, v));
    }
    {
        cplx u = x[3], v = x[7];
        x[3] = cadd(u, v);
        cplx d = csub(u, v);
        x[7] = make_float2(-RHALF * (d.x + d.y), RHALF * (d.x - d.y));
    }
#pragma unroll
    for (int b0 = 0; b0 < 8; b0 += 4) {
        {
            cplx u = x[b0], v = x[b0 + 2];
            x[b0]     = cadd(u, v);
            x[b0 + 2] = csub(u, v);
        }
        {
            cplx u = x[b0 + 1], v = x[b0 + 3];
            x[b0 + 1] = cadd(u, v);
            x[b0 + 3] = mul_posi(csub(u, v));
        }
    }
#pragma unroll
    for (int t = 0; t < 8; t += 2) {
        cplx u = x[t], v = x[t + 1];
        x[t]     = cadd(u, v);
        x[t + 1] = csub(u, v);
    }
}

// Radix-16 DIT: radix-2 stages 3..6 on x[t] = row (j + 8t), j in [0,8).
__device__ __forceinline__ void radix16_dit(cplx x[16], int j, const cplx* t128) {
    cplx wa = t128[8 * j];
#pragma unroll
    for (int t = 0; t < 16; t += 2) {
        cplx v = cmul(x[t + 1], wa);
        x[t + 1] = csub(x[t], v);
        x[t]     = cadd(x[t], v);
    }
    cplx wb0 = t128[4 * j];
    cplx wb1 = t128[4 * j + 32];
#pragma unroll
    for (int b0 = 0; b0 < 16; b0 += 4) {
        {
            cplx v = cmul(x[b0 + 2], wb0);
            x[b0 + 2] = csub(x[b0], v);
            x[b0]     = cadd(x[b0], v);
        }
        {
            cplx v = cmul(x[b0 + 3], wb1);
            x[b0 + 3] = csub(x[b0 + 1], v);
            x[b0 + 1] = cadd(x[b0 + 1], v);
        }
    }
#pragma unroll
    for (int grp = 0; grp < 16; grp += 8) {
#pragma unroll
        for (int q = 0; q < 4; q++) {
            cplx w = t128[2 * j + 16 * q];
            cplx v = cmul(x[grp + q + 4], w);
            x[grp + q + 4] = csub(x[grp + q], v);
            x[grp + q]     = cadd(x[grp + q], v);
        }
    }
#pragma unroll
    for (int t = 0; t < 8; t++) {
        cplx w = t128[j + 8 * t];
        cplx v = cmul(x[t + 8], w);
        x[t + 8] = csub(x[t], v);
        x[t]     = cadd(x[t], v);
    }
}

// Radix-16 DIF: inverse stages 6..3 with conj twiddles.
__device__ __forceinline__ void radix16_dif(cplx x[16], int j, const cplx* t128) {
#pragma unroll
    for (int t = 0; t < 8; t++) {
        cplx w = t128[j + 8 * t];
        cplx u = x[t], v = x[t + 8];
        x[t]     = cadd(u, v);
        x[t + 8] = cmulc(csub(u, v), w);
    }
#pragma unroll
    for (int grp = 0; grp < 16; grp += 8) {
#pragma unroll
        for (int q = 0; q < 4; q++) {
            cplx w = t128[2 * j + 16 * q];
            cplx u = x[grp + q], v = x[grp + q + 4];
            x[grp + q]     = cadd(u, v);
            x[grp + q + 4] = cmulc(csub(u, v), w);
        }
    }
    cplx wb0 = t128[4 * j];
    cplx wb1 = t128[4 * j + 32];
#pragma unroll
    for (int b0 = 0; b0 < 16; b0 += 4) {
        {
            cplx u = x[b0], v = x[b0 + 2];
            x[b0]     = cadd(u, v);
            x[b0 + 2] = cmulc(csub(u, v), wb0);
        }
        {
            cplx u = x[b0 + 1], v = x[b0 + 3];
            x[b0 + 1] = cadd(u, v);
            x[b0 + 3] = cmulc(csub(u, v), wb1);
        }
    }
    cplx wa = t128[8 * j];
#pragma unroll
    for (int t = 0; t < 16; t += 2) {
        cplx u = x[t], v = x[t + 1];
        x[t]     = cadd(u, v);
        x[t + 1] = cmulc(csub(u, v), wa);
    }
}

// ---------------------------------------------------------------------------
// Kernel 2: z = y1 + i*y2, Z = FFT_16000 (128x125 four-step), Hermitian split
// + pointwise multiply, phi = Re(IFFT)/N.  [verified R10/R15 FFT structure]
// PDL: zero the smem line BEFORE the grid dependency resolves, then sync.
// ---------------------------------------------------------------------------
__global__ void __launch_bounds__(THREADS)
mcb_fft_kernel(const float* __restrict__ x1, const float* __restrict__ x2,
               float* __restrict__ out) {
    extern __shared__ cplx S[];                // 16000 complex = 128000 B
    __shared__ cplx t128[128];
    __shared__ cplx t125[125];
    __shared__ cplx tS[125];

    const int tid = threadIdx.x;
    const int b   = blockIdx.x;

    // Pre-dependency work: zero the shared line (independent of extract).
    for (int i = tid; i < P_DIM; i += THREADS) S[i] = make_float2(0.0f, 0.0f);

    // Wait for the extract kernel's results (sketch + twiddle tables).
    cudaGridDependencySynchronize();

    if (tid < 128) t128[tid] = g_t128[tid];
    else if (tid < 256) { if (tid - 128 < 125) t125[tid - 128] = g_t125[tid - 128]; }
    else if (tid < 384) { if (tid - 256 < 125) tS[tid - 256]   = g_tS[tid - 256]; }
    __syncthreads();

    // scatter: y1 -> real, y2 -> imag, rows bit-reversed for the DIT stages
    for (int d = tid; d < D_DIM; d += THREADS) {
        int p = g_idx[d];
        float v = x1[b * D_DIM + d] * g_sgn[d];
        int n1 = p / 125, n2 = p - n1 * 125;
        int r = __brev(n1) >> 25;
        atomicAdd(&S[r * 125 + n2].x, v);
        p = g_idx[D_DIM + d];
        v = x2[b * D_DIM + d] * g_sgn[D_DIM + d];
        n1 = p / 125; n2 = p - n1 * 125;
        r = __brev(n1) >> 25;
        atomicAdd(&S[r * 125 + n2].y, v);
    }
    __syncthreads();

    // ---- forward radix-2 stages 0..2 (rows 8g+t, fixed col), j=0 specialized ----
    for (int idx = tid; idx < 2000; idx += THREADS) {
        int c = idx % 125;
        int g = idx / 125;
        int base = g * 1000 + c;
        cplx x[8];
#pragma unroll
        for (int t = 0; t < 8; t++) x[t] = S[base + t * 125];
        radix8_dit_j0(x);
#pragma unroll
        for (int t = 0; t < 8; t++) S[base + t * 125] = x[t];
    }
    __syncthreads();

    // ---- forward radix-2 stages 3..6 + inter-phase twiddle (radix-16) ----
    if (tid < 1000) {
        int c = tid % 125;
        int j = tid / 125;        // 0..7
        int base = j * 125 + c;
        cplx x[16];
#pragma unroll
        for (int t = 0; t < 16; t++) x[t] = S[base + t * 1000];
        radix16_dit(x, j, t128);
#pragma unroll
        for (int t = 0; t < 16; t++) {
            int k1 = j + 8 * t;
            int mm = c * k1;
            int q = mm / 125, rr = mm - q * 125;
            S[base + t * 1000] = cmul(x[t], cmul(t128[q], tS[rr]));
        }
    }
    __syncthreads();

    // ---- forward: 3 radix-5 DIF stages (length-125 row FFTs) ----
#pragma unroll
    for (int sidx = 0; sidx < 3; sidx++) {
        const int L = (sidx == 0) ? 125 : (sidx == 1) ? 25 : 5;
        const int m = L / 5;
        const int f = 125 / L;
        for (int idx = tid; idx < 3200; idx += THREADS) {
            int r  = idx & 127;
            int bj = idx >> 7;
            int j  = bj % m;
            int base = r * 125 + (bj / m) * L + j;
            cplx a[5];
            a[0] = S[base];
            a[1] = S[base + m];
            a[2] = S[base + 2 * m];
            a[3] = S[base + 3 * m];
            a[4] = S[base + 4 * m];
            bf5_fwd(a);
            int jf = j * f;
            S[base]         = a[0];
            S[base + m]     = cmul(a[1], t125[jf]);
            S[base + 2 * m] = cmul(a[2], t125[2 * jf]);
            S[base + 3 * m] = cmul(a[3], t125[3 * jf]);
            S[base + 4 * m] = cmul(a[4], t125[4 * jf]);
        }
        __syncthreads();
    }

    // ---- Hermitian split + pointwise multiply, in scrambled storage ----
    for (int k = tid; k <= 8000; k += THREADS) {
        if (k == 0) {
            cplx z = S[0];
            S[0] = make_float2(z.x * z.y, 0.0f);
        } else if (k == 8000) {
            const int addr = 64 * 125 + 62;
            cplx z = S[addr];
            S[addr] = make_float2(z.x * z.y, 0.0f);
        } else {
            int k1 = k & 127, k2 = k >> 7;
            int pa = k1 * 125 + dr5(k2);
            int kp = P_DIM - k;
            int k1p = kp & 127, k2p = kp >> 7;
            int pb = k1p * 125 + dr5(k2p);
            cplx A = S[pa];
            cplx Bv = S[pb];
            float F1r = 0.5f * (A.x + Bv.x), F1i = 0.5f * (A.y - Bv.y);
            float F2r = 0.5f * (A.y + Bv.y), F2i = 0.5f * (Bv.x - A.x);
            float Hr = F1r * F2r - F1i * F2i;
            float Hi = F1r * F2i + F1i * F2r;
            S[pa] = make_float2(Hr,  Hi);
            S[pb] = make_float2(Hr, -Hi);
        }
    }
    __syncthreads();

    // ---- inverse: 3 radix-5 DIT stages (rows), conj twiddles ----
#pragma unroll
    for (int sidx = 0; sidx < 3; sidx++) {
        const int L = (sidx == 0) ? 5 : (sidx == 1) ? 25 : 125;
        const int m = L / 5;
        const int f = 125 / L;
        for (int idx = tid; idx < 3200; idx += THREADS) {
            int r  = idx & 127;
            int bj = idx >> 7;
            int j  = bj % m;
            int base = r * 125 + (bj / m) * L + j;
            int jf = j * f;
            cplx a[5];
            a[0] = S[base];
            a[1] = cmulc(S[base + m],     t125[jf]);
            a[2] = cmulc(S[base + 2 * m], t125[2 * jf]);
            a[3] = cmulc(S[base + 3 * m], t125[3 * jf]);
            a[4] = cmulc(S[base + 4 * m], t125[4 * jf]);
            bf5_inv(a);
            S[base]         = a[0];
            S[base + m]     = a[1];
            S[base + 2 * m] = a[2];
            S[base + 3 * m] = a[3];
            S[base + 4 * m] = a[4];
        }
        __syncthreads();
    }

    // ---- inverse inter-phase twiddle (conj) + radix-2 stages 6..3 (radix-16) ----
    if (tid < 1000) {
        int c = tid % 125;
        int j = tid / 125;
        int base = j * 125 + c;
        cplx x[16];
#pragma unroll
        for (int t = 0; t < 16; t++) {
            int k1 = j + 8 * t;
            int mm = c * k1;
            int q = mm / 125, rr = mm - q * 125;
            x[t] = cmulc(S[base + t * 1000], cmul(t128[q], tS[rr]));
        }
        radix16_dif(x, j, t128);
#pragma unroll
        for (int t = 0; t < 16; t++) S[base + t * 1000] = x[t];
    }
    __syncthreads();

    // ---- inverse radix-2 stages 2..0 (j=0 specialized), fused with output ----
    const float scale = 1.0f / 16000.0f;
    for (int idx = tid; idx < 2000; idx += THREADS) {
        int c = idx % 125;
        int g = idx / 125;
        int base = g * 1000 + c;
        cplx x[8];
#pragma unroll
        for (int t = 0; t < 8; t++) x[t] = S[base + t * 125];
        radix8_dif_j0(x);
#pragma unroll
        for (int t = 0; t < 8; t++) {
            int n1 = __brev(8 * g + t) >> 25;
            out[b * P_DIM + n1 * 125 + c] = x[t].x * scale;
        }
    }
}

extern "C" void kernel_launch(void* const* d_in, const int* in_sizes, int n_in,
                              void* d_out, int out_size) {
    const float* x1 = (const float*)d_in[0];
    const float* x2 = (const float*)d_in[1];
    const float* C1 = (const float*)d_in[2];
    const float* C2 = (const float*)d_in[3];
    float* out = (float*)d_out;

    extract_kernel<<<2 * D_DIM + 1, EX_THREADS>>>(C1, C2);

    const size_t smem = (size_t)P_DIM * sizeof(cplx);  // 128000 B
    cudaFuncSetAttribute(mcb_fft_kernel,
                         cudaFuncAttributeMaxDynamicSharedMemorySize, (int)smem);

    // PDL launch: FFT may begin (smem zeroing) while extract drains.
    cudaLaunchConfig_t cfg = {};
    cfg.gridDim  = dim3(B_BATCH, 1, 1);
    cfg.blockDim = dim3(THREADS, 1, 1);
    cfg.dynamicSmemBytes = smem;
    cfg.stream = 0;
    cudaLaunchAttribute attrs[1];
    attrs[0].id = cudaLaunchAttributeProgrammaticStreamSerialization;
    attrs[0].val.programmaticStreamSerializationAllowed = 1;
    cfg.attrs = attrs;
    cfg.numAttrs = 1;
    cudaError_t err = cudaLaunchKernelEx(&cfg, mcb_fft_kernel, x1, x2, out);
    if (err != cudaSuccess) {
        // Fallback: plain launch (cudaGridDependencySynchronize is a no-op).
        mcb_fft_kernel<<<B_BATCH, THREADS, smem>>>(x1, x2, out);
    }
}